// round 14
// baseline (speedup 1.0000x reference)
#include <cuda_runtime.h>

#define BB 16
#define CC 80
#define HH 128
#define WW 128
#define NN 50
#define CANDK 100
#define FTPB 256
#define FBLK 1024
#define BTPB 1024
#define NBATCH 32
#define HSZ 1024
#define HEMPTY 0xFFFFFFFFu
#define KARR 2048               // window <= 38x38 = 1444, padded to BTPB mult
#define LN2 0.6931471805599453

// Partials (each slot written unconditionally every launch) + done counter
// (zero at load; reset by the combining block each launch -> replay-safe).
__device__ double g_focal[FBLK];
__device__ float  g_corr[BB];
__device__ float  g_off[BB];
__device__ float  g_size[BB];
__device__ int    g_npos[BB];
__device__ int    g_done;

__device__ __forceinline__ float clampp(float x) {
    return fminf(fmaxf(x, 1e-4f), 0.9999f);
}
// p^2 * lg2(1-p): ln2 factored out per block
__device__ __forceinline__ float nb2(float x) {
    float p = clampp(x);
    return p * p * __log2f(1.0f - p);
}

// ===========================================================================
// Kernel 1: focal base stream — byte-faithful replica of the R2/R3 kernel
// that profiled at 17.0-17.5us / ~5 TB/s. No tail code, 32B smem.
// ===========================================================================
__global__ void focal_base_kernel(const float4* __restrict__ cls, int total4) {
    float a0 = 0.f, a1 = 0.f, a2 = 0.f, a3 = 0.f;
    int stride = gridDim.x * blockDim.x;
    int i = blockIdx.x * blockDim.x + threadIdx.x;
    for (; i + 3 * stride < total4; i += 4 * stride) {
        float4 v0 = cls[i];
        float4 v1 = cls[i + stride];
        float4 v2 = cls[i + 2 * stride];
        float4 v3 = cls[i + 3 * stride];
        a0 += nb2(v0.x) + nb2(v0.y) + nb2(v0.z) + nb2(v0.w);
        a1 += nb2(v1.x) + nb2(v1.y) + nb2(v1.z) + nb2(v1.w);
        a2 += nb2(v2.x) + nb2(v2.y) + nb2(v2.z) + nb2(v2.w);
        a3 += nb2(v3.x) + nb2(v3.y) + nb2(v3.z) + nb2(v3.w);
    }
    for (; i < total4; i += stride) {
        float4 v = cls[i];
        a0 += nb2(v.x) + nb2(v.y) + nb2(v.z) + nb2(v.w);
    }
    __shared__ float ws[8];
    float v = (a0 + a1) + (a2 + a3);
    int lane = threadIdx.x & 31, w = threadIdx.x >> 5;
    #pragma unroll
    for (int o = 16; o; o >>= 1) v += __shfl_down_sync(0xffffffffu, v, o);
    if (lane == 0) ws[w] = v;
    __syncthreads();
    if (threadIdx.x == 0) {
        float s = 0.f;
        #pragma unroll
        for (int k = 0; k < 8; k++) s += ws[k];
        g_focal[blockIdx.x] = (double)s * (double)LN2;
    }
}

// ===========================================================================
// Kernel 2: batch targets (runs ALONE after focal -> idle memory system)
//   blocks 0..15  : type A (gt hash-dedup + focal corrections)
//   blocks 16..31 : type B (top-CANDK select + offset/size loss)
// Last block to finish performs the final combine (g_focal visible by
// stream order).
// ===========================================================================
union SmemU {
    struct { unsigned hkey[HSZ]; unsigned hval[HSZ]; } a;              // 8 KB
    struct {
        unsigned keys_v[KARR];
        unsigned short keys_i[KARR];
        float o0[KARR], o1[KARR], s0[KARR], s1[KARR];                  // 44 KB
    } b;
};

__global__ void __launch_bounds__(BTPB, 1)
batch_kernel(const float* __restrict__ cls,
             const float* __restrict__ offp,
             const float* __restrict__ sizep,
             const float* __restrict__ gt_box,
             const int* __restrict__ gt_class,
             float* __restrict__ out) {
    __shared__ SmemU u;
    __shared__ int hist[256];
    __shared__ int wsum[32];
    __shared__ float wsf[32];
    __shared__ double wsd[32];
    __shared__ float s_w[NN], s_h[NN];
    __shared__ int s_ch[NN];
    __shared__ int s_last;
    __shared__ unsigned s_pfx;
    __shared__ int s_kth;
    __shared__ int s_eq;
    __shared__ int s_flag;

    const int tid = threadIdx.x;
    const int lane = tid & 31, wrp = tid >> 5;

    if (blockIdx.x < BB) {
        // ========== type A: gt hash-dedup + focal corrections ==========
        const int b = blockIdx.x;
        const float* clsb = cls + (size_t)b * CC * HH * WW;

        if (tid < HSZ) { u.a.hkey[tid] = HEMPTY; u.a.hval[tid] = 0u; }
        __syncthreads();

        if (tid < NN) {
            int clsv = gt_class[b * NN + tid];
            float4 bx = ((const float4*)gt_box)[b * NN + tid];
            if (clsv != -1) {
                int ch = max(clsv, 0);
                float wv = bx.z - bx.x;
                float hv = bx.w - bx.y;
                int cx = (int)floorf(floorf(wv * 0.5f) * 0.25f);
                int cy = (int)floorf(floorf(hv * 0.5f) * 0.25f);
                const float ONE_V = 0.6065306597126334f;   // exp(-0.5)
                const float TWO_V = 0.36787944117144233f;  // exp(-1.0)
                bool interior = (cx >= 1) && (cy >= 1) && (cx + 1 < HH) && (cy + 1 < WW);
                #pragma unroll
                for (int k = 0; k < 9; k++) {
                    int dx = k / 3 - 1, dy = k % 3 - 1;
                    float vv;
                    if (dx == 0 && dy == 0) {
                        if (cx < 0 || cx >= HH || cy < 0 || cy >= WW) continue;
                        vv = 1.0f;
                    } else {
                        if (!interior) continue;
                        vv = (dx != 0 && dy != 0) ? TWO_V : ONE_V;
                    }
                    unsigned cell = (unsigned)(((ch * HH + cx + dx) * WW) + cy + dy);
                    unsigned slot = (cell * 2654435761u) & (HSZ - 1);
                    while (true) {
                        unsigned prev = atomicCAS(&u.a.hkey[slot], HEMPTY, cell);
                        if (prev == HEMPTY || prev == cell) {
                            atomicMax(&u.a.hval[slot], __float_as_uint(vv));
                            break;
                        }
                        slot = (slot + 1) & (HSZ - 1);
                    }
                }
            }
        }
        __syncthreads();

        float corr = 0.f;
        if (tid < HSZ) {   // one slot per thread
            unsigned cell = u.a.hkey[tid];
            if (cell != HEMPTY) {
                float g = __uint_as_float(u.a.hval[tid]);
                float p = clampp(clsb[cell]);
                float base = p * p * __logf(1.0f - p);
                float actual;
                if (g == 1.0f) {
                    float q = 1.0f - p, q2 = q * q;
                    actual = q2 * q2 * __logf(p);
                } else {
                    float q = 1.0f - g, q2 = q * q;
                    actual = q2 * q2 * base;
                }
                corr = actual - base;
            }
        }
        #pragma unroll
        for (int o = 16; o; o >>= 1) corr += __shfl_down_sync(0xffffffffu, corr, o);
        if (lane == 0) wsf[wrp] = corr;
        __syncthreads();
        if (tid == 0) {
            float s = 0.f;
            #pragma unroll
            for (int k = 0; k < BTPB / 32; k++) s += wsf[k];
            g_corr[b] = s;
        }
    } else {
        // ========== type B: top-CANDK select + offset/size loss ==========
        const int b = blockIdx.x - BB;
        const float* clsb = cls + (size_t)b * CC * HH * WW;

        if (tid == 0) s_last = -1;
        __syncthreads();
        if (tid < NN) {
            int clsv = gt_class[b * NN + tid];
            float4 bx = ((const float4*)gt_box)[b * NN + tid];
            s_w[tid] = bx.z - bx.x;
            s_h[tid] = bx.w - bx.y;
            s_ch[tid] = max(clsv, 0);
            if (clsv != -1) atomicMax(&s_last, tid);
        }
        __syncthreads();

        int last = s_last;
        float sO = 0.f, sS = 0.f;
        int K = 0;
        float wv = 0.f, hv = 0.f;
        if (last >= 0) {
            wv = s_w[last];
            hv = s_h[last];
            int ch = s_ch[last];
            int cx = (int)floorf(floorf(wv * 0.5f) * 0.25f);
            int cy = (int)floorf(floorf(hv * 0.5f) * 0.25f);
            int w4 = (int)floorf(wv * 0.25f);
            int h4 = (int)floorf(hv * 0.25f);
            int left   = max((cx - (w4 >> 1)) >> 1, 0);   // >>1 == floor-div 2
            int right  = min((cx + (w4 >> 1)) >> 1, HH / 2);
            int top    = max((cy - (h4 >> 1)) >> 1, 0);
            int bottom = min((cy + (h4 >> 1)) >> 1, WW / 2);
            int wr = right - left, hc = bottom - top;
            int M = (wr > 0 && hc > 0) ? wr * hc : 0;
            M = min(M, KARR);    // guaranteed by input ranges; safety clamp
            K = min(CANDK, M);
            if (M > 0) {
                int Mr = (M + BTPB - 1) & ~(BTPB - 1);   // <= KARR
                // ONE global phase: window values + off/size prefetch together
                for (int t = tid; t < M; t += BTPB) {
                    int r = left + t / hc;
                    int c = top + t % hc;
                    int rc = r * WW + c;
                    float vv = clsb[ch * HH * WW + rc];
                    u.b.keys_v[t] = __float_as_uint(vv);
                    u.b.keys_i[t] = (unsigned short)rc;
                    u.b.o0[t] = offp[(b * 2 + 0) * HH * WW + rc];
                    u.b.o1[t] = offp[(b * 2 + 1) * HH * WW + rc];
                    u.b.s0[t] = sizep[(b * 2 + 0) * HH * WW + rc];
                    u.b.s1[t] = sizep[(b * 2 + 1) * HH * WW + rc];
                }
                for (int t = M + tid; t < Mr; t += BTPB) u.b.keys_v[t] = 0xFFFFFFFFu;
                __syncthreads();

                unsigned V = 0xFFFFFFFFu;   // M <= K: select all
                unsigned Ti = 0xFFFFu;      // inclusive index threshold at v==V
                if (M > K) {
                    // ---- 4-pass radix-select of Kth smallest VALUE ----
                    if (tid == 0) { s_pfx = 0u; s_kth = K; }
                    __syncthreads();
                    #pragma unroll
                    for (int pi = 0; pi < 4; pi++) {
                        const int d = 24 - 8 * pi;
                        if (tid < 256) hist[tid] = 0;
                        __syncthreads();
                        unsigned pfx = s_pfx;
                        int kth = s_kth;
                        for (int i = tid; i < Mr; i += BTPB) {
                            unsigned v = u.b.keys_v[i];
                            if (pi == 0 || (v >> (d + 8)) == pfx)
                                atomicAdd(&hist[(v >> d) & 255], 1);
                        }
                        __syncthreads();
                        if (tid < 256) {
                            int h0 = hist[tid];
                            int h = h0;
                            #pragma unroll
                            for (int o = 1; o < 32; o <<= 1) {
                                int n = __shfl_up_sync(0xffffffffu, h, o);
                                if (lane >= o) h += n;
                            }
                            if (lane == 31) wsum[wrp] = h;
                            __syncwarp();
                        }
                        __syncthreads();
                        if (tid < 8) {
                            int s = wsum[tid];
                            #pragma unroll
                            for (int o = 1; o < 8; o <<= 1) {
                                int n = __shfl_up_sync(0xffu, s, o);
                                if (tid >= o) s += n;
                            }
                            wsum[tid] = s;
                        }
                        __syncthreads();
                        if (tid < 256) {
                            int h0 = hist[tid];
                            int h = h0;
                            #pragma unroll
                            for (int o = 1; o < 32; o <<= 1) {
                                int n = __shfl_up_sync(0xffffffffu, h, o);
                                if (lane >= o) h += n;
                            }
                            int cum = h + (wrp ? wsum[wrp - 1] : 0);
                            if (cum - h0 < kth && kth <= cum) {   // one thread
                                s_kth = kth - (cum - h0);
                                s_pfx = (pfx << 8) | (unsigned)tid;
                                if (pi == 3) s_eq = h0;
                            }
                        }
                        __syncthreads();
                    }
                    V = s_pfx;
                    int needed = s_kth, eqc = s_eq;
                    if (needed < eqc) {
                        // ---- rare: tie-break on index (2x7-bit radix) ----
                        if (tid == 0) s_pfx = 0u;
                        __syncthreads();
                        #pragma unroll
                        for (int pi = 0; pi < 2; pi++) {
                            const int d = 7 - 7 * pi;
                            if (tid < 128) hist[tid] = 0;
                            __syncthreads();
                            unsigned pfx = s_pfx;
                            int kth = s_kth;
                            for (int i = tid; i < Mr; i += BTPB) {
                                if (u.b.keys_v[i] == V) {
                                    unsigned ix = u.b.keys_i[i];
                                    if (pi == 0 || (ix >> (d + 7)) == pfx)
                                        atomicAdd(&hist[(ix >> d) & 127], 1);
                                }
                            }
                            __syncthreads();
                            if (tid < 128) {
                                int h0 = hist[tid];
                                int h = h0;
                                #pragma unroll
                                for (int o = 1; o < 32; o <<= 1) {
                                    int n = __shfl_up_sync(0xffffffffu, h, o);
                                    if (lane >= o) h += n;
                                }
                                if (lane == 31) wsum[wrp] = h;
                                __syncwarp();
                            }
                            __syncthreads();
                            if (tid < 4) {
                                int s = wsum[tid];
                                #pragma unroll
                                for (int o = 1; o < 4; o <<= 1) {
                                    int n = __shfl_up_sync(0xfu, s, o);
                                    if (tid >= o) s += n;
                                }
                                wsum[tid] = s;
                            }
                            __syncthreads();
                            if (tid < 128) {
                                int h0 = hist[tid];
                                int h = h0;
                                #pragma unroll
                                for (int o = 1; o < 32; o <<= 1) {
                                    int n = __shfl_up_sync(0xffffffffu, h, o);
                                    if (lane >= o) h += n;
                                }
                                int cum = h + (wrp ? wsum[wrp - 1] : 0);
                                if (cum - h0 < kth && kth <= cum) {
                                    s_kth = kth - (cum - h0);
                                    s_pfx = (s_pfx << 7) | (unsigned)tid;
                                }
                            }
                            __syncthreads();
                        }
                        Ti = s_pfx;   // include idx <= Ti among v==V
                    }
                }

                float cxf = wv * 0.5f * 0.25f;
                float cyf = hv * 0.5f * 0.25f;
                float off0 = cxf - floorf(cxf);
                float off1 = cyf - floorf(cyf);
                // final accumulation: shared-only (no global gather)
                for (int t = tid; t < M; t += BTPB) {
                    unsigned v = u.b.keys_v[t];
                    unsigned ix = u.b.keys_i[t];
                    if (v < V || (v == V && ix <= Ti)) {
                        sO += fabsf(u.b.o0[t] - off0) + fabsf(u.b.o1[t] - off1);
                        sS += fabsf(u.b.s0[t] - wv) + fabsf(u.b.s1[t] - hv);
                    }
                }
            }
        }
        #pragma unroll
        for (int o = 16; o; o >>= 1) {
            sO += __shfl_down_sync(0xffffffffu, sO, o);
            sS += __shfl_down_sync(0xffffffffu, sS, o);
        }
        __syncthreads();
        if (lane == 0) { wsf[wrp] = sO; wsd[wrp] = (double)sS; }
        __syncthreads();
        if (tid == 0) {
            float aO = 0.f, aS = 0.f;
            #pragma unroll
            for (int k = 0; k < BTPB / 32; k++) { aO += wsf[k]; aS += (float)wsd[k]; }
            g_off[b] = aO;
            g_size[b] = aS;
            g_npos[b] = K;
        }
    }

    // ================= last-block combine =================
    __threadfence();
    __syncthreads();
    if (tid == 0) s_flag = (atomicAdd(&g_done, 1) == NBATCH - 1);
    __syncthreads();
    if (s_flag) {
        __threadfence();
        // g_focal written by the focal kernel (prior node in the stream)
        double acc = (tid < FBLK) ? g_focal[tid] : 0.0;
        #pragma unroll
        for (int o = 16; o; o >>= 1) acc += __shfl_down_sync(0xffffffffu, acc, o);
        if (lane == 0) wsd[wrp] = acc;
        __syncthreads();
        if (tid == 0) {
            double fsum = 0.0;
            #pragma unroll
            for (int k = 0; k < BTPB / 32; k++) fsum += wsd[k];
            double corr = 0.0, offs = 0.0, szs = 0.0;
            int npos = 0;
            for (int b2 = 0; b2 < BB; b2++) {
                corr += (double)g_corr[b2];
                offs += (double)g_off[b2];
                szs  += (double)g_size[b2];
                npos += g_npos[b2];
            }
            double np = (double)max(npos, 1);
            double cls_loss = -(fsum + corr) / (double)(BB * HH * WW);
            out[0] = (float)(cls_loss + 0.1 * (szs / np) + (offs / np));
            g_done = 0;   // reset for next graph replay
        }
    }
}

extern "C" void kernel_launch(void* const* d_in, const int* in_sizes, int n_in,
                              void* d_out, int out_size) {
    const float* cls_pred    = (const float*)d_in[0];
    const float* offset_pred = (const float*)d_in[1];
    const float* size_pred   = (const float*)d_in[2];
    const float* gt_box      = (const float*)d_in[3];
    const int*   gt_class    = (const int*)d_in[4];
    float* out = (float*)d_out;
    (void)in_sizes; (void)n_in; (void)out_size;

    int total4 = (BB * CC * HH * WW) / 4;
    // Focal first, alone: the exact configuration that profiled at ~5 TB/s.
    focal_base_kernel<<<FBLK, FTPB>>>((const float4*)cls_pred, total4);
    // Batch second, alone on an idle memory system; includes final combine.
    batch_kernel<<<NBATCH, BTPB>>>(cls_pred, offset_pred, size_pred,
                                   gt_box, gt_class, out);
}

// round 15
// speedup vs baseline: 1.0837x; 1.0837x over previous
#include <cuda_runtime.h>

#define BB 16
#define CC 80
#define HH 128
#define WW 128
#define NN 50
#define CANDK 100
#define TPB 512
#define NBATCH 32
#define FBLK 560
#define NBLK (FBLK + NBATCH)    // 592 = 148 SMs * 4 blocks
#define HSZ 1024
#define HEMPTY 0xFFFFFFFFu
#define KPAD 2048               // bitonic size (pow2 >= max window 1369)
#define KARR 1536               // plane arrays (window <= 1444? clamp 1536)
#define LN2 0.6931471805599453

// Partials (each slot written unconditionally every launch) + done counter
// (zero at load; reset by the combining block each launch -> replay-safe).
__device__ double g_focal[FBLK];
__device__ float  g_corr[BB];
__device__ float  g_off[BB];
__device__ float  g_size[BB];
__device__ int    g_npos[BB];
__device__ int    g_done;

__device__ __forceinline__ float clampp(float x) {
    return fminf(fmaxf(x, 1e-4f), 0.9999f);
}
// p^2 * lg2(1-p): ln2 factored out once per block
__device__ __forceinline__ float nb2(float x) {
    float p = clampp(x);
    return p * p * __log2f(1.0f - p);
}

union SmemU {
    struct { unsigned hkey[HSZ]; unsigned hval[HSZ]; } a;              // 8 KB
    struct {
        unsigned long long keys[KPAD];                 // 16 KB
        float o0[KARR], o1[KARR], s0[KARR], s1[KARR];  // 24 KB
    } b;                                               // 40 KB total
};

__global__ void __launch_bounds__(TPB, 4)
fused_kernel(const float4* __restrict__ cls4,
             const float* __restrict__ cls,
             const float* __restrict__ offp,
             const float* __restrict__ sizep,
             const float* __restrict__ gt_box,
             const int* __restrict__ gt_class,
             float* __restrict__ out) {
    __shared__ SmemU u;
    __shared__ float wsf[16];
    __shared__ double wsd[16];
    __shared__ float s_w[NN], s_h[NN];
    __shared__ int s_ch[NN];
    __shared__ int s_last;
    __shared__ int s_flag;

    const int tid = threadIdx.x;
    const int lane = tid & 31, wrp = tid >> 5;

    if (blockIdx.x >= NBATCH) {
        // ================= focal partial (blocks 32..591) =================
        const int total4 = BB * CC * HH * WW / 4;
        const int stride = FBLK * TPB;
        int i = (blockIdx.x - NBATCH) * TPB + tid;
        float a0 = 0.f, a1 = 0.f, a2 = 0.f, a3 = 0.f;
        for (; i + 3 * stride < total4; i += 4 * stride) {
            float4 v0 = cls4[i];
            float4 v1 = cls4[i + stride];
            float4 v2 = cls4[i + 2 * stride];
            float4 v3 = cls4[i + 3 * stride];
            a0 += nb2(v0.x) + nb2(v0.y) + nb2(v0.z) + nb2(v0.w);
            a1 += nb2(v1.x) + nb2(v1.y) + nb2(v1.z) + nb2(v1.w);
            a2 += nb2(v2.x) + nb2(v2.y) + nb2(v2.z) + nb2(v2.w);
            a3 += nb2(v3.x) + nb2(v3.y) + nb2(v3.z) + nb2(v3.w);
        }
        for (; i < total4; i += stride) {
            float4 v = cls4[i];
            a0 += nb2(v.x) + nb2(v.y) + nb2(v.z) + nb2(v.w);
        }
        float v = (a0 + a1) + (a2 + a3);
        #pragma unroll
        for (int o = 16; o; o >>= 1) v += __shfl_down_sync(0xffffffffu, v, o);
        if (lane == 0) wsf[wrp] = v;
        __syncthreads();
        if (tid == 0) {
            float s = 0.f;
            #pragma unroll
            for (int k = 0; k < 16; k++) s += wsf[k];
            g_focal[blockIdx.x - NBATCH] = (double)s * LN2;
        }
    } else if (blockIdx.x < BB) {
        // ========== type A: gt hash-dedup + focal corrections ==========
        const int b = blockIdx.x;
        const float* clsb = cls + (size_t)b * CC * HH * WW;

        for (int s = tid; s < HSZ; s += TPB) { u.a.hkey[s] = HEMPTY; u.a.hval[s] = 0u; }
        __syncthreads();

        if (tid < NN) {
            int clsv = gt_class[b * NN + tid];
            float4 bx = ((const float4*)gt_box)[b * NN + tid];
            if (clsv != -1) {
                int ch = max(clsv, 0);
                float wv = bx.z - bx.x;
                float hv = bx.w - bx.y;
                int cx = (int)floorf(floorf(wv * 0.5f) * 0.25f);
                int cy = (int)floorf(floorf(hv * 0.5f) * 0.25f);
                const float ONE_V = 0.6065306597126334f;   // exp(-0.5)
                const float TWO_V = 0.36787944117144233f;  // exp(-1.0)
                bool interior = (cx >= 1) && (cy >= 1) && (cx + 1 < HH) && (cy + 1 < WW);
                for (int k = 0; k < 9; k++) {   // compact, no unroll
                    int dx = k / 3 - 1, dy = k % 3 - 1;
                    float vv;
                    if (dx == 0 && dy == 0) {
                        if (cx < 0 || cx >= HH || cy < 0 || cy >= WW) continue;
                        vv = 1.0f;
                    } else {
                        if (!interior) continue;
                        vv = (dx != 0 && dy != 0) ? TWO_V : ONE_V;
                    }
                    unsigned cell = (unsigned)(((ch * HH + cx + dx) * WW) + cy + dy);
                    unsigned slot = (cell * 2654435761u) & (HSZ - 1);
                    while (true) {
                        unsigned prev = atomicCAS(&u.a.hkey[slot], HEMPTY, cell);
                        if (prev == HEMPTY || prev == cell) {
                            atomicMax(&u.a.hval[slot], __float_as_uint(vv));
                            break;
                        }
                        slot = (slot + 1) & (HSZ - 1);
                    }
                }
            }
        }
        __syncthreads();

        float corr = 0.f;
        for (int s = tid; s < HSZ; s += TPB) {
            unsigned cell = u.a.hkey[s];
            if (cell != HEMPTY) {
                float g = __uint_as_float(u.a.hval[s]);
                float p = clampp(clsb[cell]);
                float base = p * p * __logf(1.0f - p);
                float actual;
                if (g == 1.0f) {
                    float q = 1.0f - p, q2 = q * q;
                    actual = q2 * q2 * __logf(p);
                } else {
                    float q = 1.0f - g, q2 = q * q;
                    actual = q2 * q2 * base;
                }
                corr += actual - base;
            }
        }
        #pragma unroll
        for (int o = 16; o; o >>= 1) corr += __shfl_down_sync(0xffffffffu, corr, o);
        if (lane == 0) wsf[wrp] = corr;
        __syncthreads();
        if (tid == 0) {
            float s = 0.f;
            #pragma unroll
            for (int k = 0; k < 16; k++) s += wsf[k];
            g_corr[b] = s;
        }
    } else {
        // ========== type B: top-CANDK select (bitonic) + off/size loss ==========
        const int b = blockIdx.x - BB;
        const float* clsb = cls + (size_t)b * CC * HH * WW;

        if (tid == 0) s_last = -1;
        __syncthreads();
        if (tid < NN) {
            int clsv = gt_class[b * NN + tid];
            float4 bx = ((const float4*)gt_box)[b * NN + tid];
            s_w[tid] = bx.z - bx.x;
            s_h[tid] = bx.w - bx.y;
            s_ch[tid] = max(clsv, 0);
            if (clsv != -1) atomicMax(&s_last, tid);
        }
        __syncthreads();

        int last = s_last;
        float sO = 0.f, sS = 0.f;
        int K = 0;
        float wv = 0.f, hv = 0.f;
        if (last >= 0) {
            wv = s_w[last];
            hv = s_h[last];
            int ch = s_ch[last];
            int cx = (int)floorf(floorf(wv * 0.5f) * 0.25f);
            int cy = (int)floorf(floorf(hv * 0.5f) * 0.25f);
            int w4 = (int)floorf(wv * 0.25f);
            int h4 = (int)floorf(hv * 0.25f);
            int left   = max((cx - (w4 >> 1)) >> 1, 0);   // >>1 == floor-div 2
            int right  = min((cx + (w4 >> 1)) >> 1, HH / 2);
            int top    = max((cy - (h4 >> 1)) >> 1, 0);
            int bottom = min((cy + (h4 >> 1)) >> 1, WW / 2);
            int wr = right - left, hc = bottom - top;
            int M = (wr > 0 && hc > 0) ? wr * hc : 0;
            M = min(M, KARR);    // guaranteed by input ranges; safety clamp
            K = min(CANDK, M);
            if (M > 0) {
                // ONE global phase: window values + off/size prefetch together.
                // key = valbits<<32 | t : ascending sort == (val asc, flat-idx asc)
                // because t-order within the window equals flat-idx order.
                for (int t = tid; t < M; t += TPB) {
                    int r = left + t / hc;
                    int c = top + t % hc;
                    int rc = r * WW + c;
                    float vv = clsb[ch * HH * WW + rc];
                    u.b.keys[t] = (((unsigned long long)__float_as_uint(vv)) << 32)
                                | (unsigned)t;
                    u.b.o0[t] = offp[(b * 2 + 0) * HH * WW + rc];
                    u.b.o1[t] = offp[(b * 2 + 1) * HH * WW + rc];
                    u.b.s0[t] = sizep[(b * 2 + 0) * HH * WW + rc];
                    u.b.s1[t] = sizep[(b * 2 + 1) * HH * WW + rc];
                }
                for (int t = M + tid; t < KPAD; t += TPB) u.b.keys[t] = ~0ull;
                __syncthreads();

                // compact bitonic sort, ascending (tiny code footprint)
                for (int k = 2; k <= KPAD; k <<= 1) {
                    for (int j = k >> 1; j > 0; j >>= 1) {
                        for (int i = tid; i < KPAD; i += TPB) {
                            int ixj = i ^ j;
                            if (ixj > i) {
                                unsigned long long x = u.b.keys[i];
                                unsigned long long y = u.b.keys[ixj];
                                bool up = ((i & k) == 0);
                                if ((x > y) == up) {
                                    u.b.keys[i] = y;
                                    u.b.keys[ixj] = x;
                                }
                            }
                        }
                        __syncthreads();
                    }
                }

                float cxf = wv * 0.5f * 0.25f;
                float cyf = hv * 0.5f * 0.25f;
                float off0 = cxf - floorf(cxf);
                float off1 = cyf - floorf(cyf);
                // selected = first K sorted entries; all data already in smem
                if (tid < K) {
                    int t = (int)(u.b.keys[tid] & 0xffffffffu);
                    sO = fabsf(u.b.o0[t] - off0) + fabsf(u.b.o1[t] - off1);
                    sS = fabsf(u.b.s0[t] - wv) + fabsf(u.b.s1[t] - hv);
                }
            }
        }
        #pragma unroll
        for (int o = 16; o; o >>= 1) {
            sO += __shfl_down_sync(0xffffffffu, sO, o);
            sS += __shfl_down_sync(0xffffffffu, sS, o);
        }
        __syncthreads();
        if (lane == 0) { wsf[wrp] = sO; wsd[wrp] = (double)sS; }
        __syncthreads();
        if (tid == 0) {
            float aO = 0.f, aS = 0.f;
            #pragma unroll
            for (int k = 0; k < 16; k++) { aO += wsf[k]; aS += (float)wsd[k]; }
            g_off[b] = aO;
            g_size[b] = aS;
            g_npos[b] = K;
        }
    }

    // ================= last-block combine =================
    __threadfence();
    __syncthreads();
    if (tid == 0) s_flag = (atomicAdd(&g_done, 1) == NBLK - 1);
    __syncthreads();
    if (s_flag) {
        __threadfence();
        double acc = 0.0;
        for (int i2 = tid; i2 < FBLK; i2 += TPB) acc += g_focal[i2];
        #pragma unroll
        for (int o = 16; o; o >>= 1) acc += __shfl_down_sync(0xffffffffu, acc, o);
        if (lane == 0) wsd[wrp] = acc;
        __syncthreads();
        if (tid == 0) {
            double fsum = 0.0;
            #pragma unroll
            for (int k = 0; k < 16; k++) fsum += wsd[k];
            double corr = 0.0, offs = 0.0, szs = 0.0;
            int npos = 0;
            for (int b2 = 0; b2 < BB; b2++) {
                corr += (double)g_corr[b2];
                offs += (double)g_off[b2];
                szs  += (double)g_size[b2];
                npos += g_npos[b2];
            }
            double np = (double)max(npos, 1);
            double cls_loss = -(fsum + corr) / (double)(BB * HH * WW);
            out[0] = (float)(cls_loss + 0.1 * (szs / np) + (offs / np));
            g_done = 0;   // reset for next graph replay
        }
    }
}

extern "C" void kernel_launch(void* const* d_in, const int* in_sizes, int n_in,
                              void* d_out, int out_size) {
    const float* cls_pred    = (const float*)d_in[0];
    const float* offset_pred = (const float*)d_in[1];
    const float* size_pred   = (const float*)d_in[2];
    const float* gt_box      = (const float*)d_in[3];
    const int*   gt_class    = (const int*)d_in[4];
    float* out = (float*)d_out;
    (void)in_sizes; (void)n_in; (void)out_size;

    fused_kernel<<<NBLK, TPB>>>((const float4*)cls_pred, cls_pred,
                                offset_pred, size_pred, gt_box, gt_class, out);
}

// round 16
// speedup vs baseline: 1.2452x; 1.1490x over previous
#include <cuda_runtime.h>

#define BB 16
#define CC 80
#define HH 128
#define WW 128
#define NN 50
#define CANDK 100
#define TPB 256
#define NSM 148
#define BRES 4                  // residues 0..3 -> batch SMs (4 SMs x 8 blocks)
#define NBATCH 32
#define FBLK 1152               // 144 residues x 8 layers
#define NBLK 1184               // exactly one wave: 148 SMs x 8 blocks
#define HSZ 1024
#define HEMPTY 0xFFFFFFFFu
#define KARR 1536               // window <= 37x37 = 1369, safety-padded
#define LN2 0.6931471805599453

// Partials (each slot written unconditionally every launch) + done counter
// (zero at load; reset by the combining block each launch -> replay-safe).
__device__ double g_focal[FBLK];
__device__ float  g_corr[BB];
__device__ float  g_off[BB];
__device__ float  g_size[BB];
__device__ int    g_npos[BB];
__device__ int    g_done;

__device__ __forceinline__ float clampp(float x) {
    return fminf(fmaxf(x, 1e-4f), 0.9999f);
}
// p^2 * lg2(1-p): ln2 factored out once per block
__device__ __forceinline__ float nb2(float x) {
    float p = clampp(x);
    return p * p * __log2f(1.0f - p);
}

union SmemU {
    struct { unsigned hkey[HSZ]; unsigned hval[HSZ]; } a;   // 8 KB
    struct {
        unsigned keys_v[KARR];        // value bits (positive floats)
        unsigned short keys_i[KARR];  // flat 14-bit index
    } b;                                                    // 9 KB
};

__global__ void __launch_bounds__(TPB, 8)
fused_kernel(const float4* __restrict__ cls4,
             const float* __restrict__ cls,
             const float* __restrict__ offp,
             const float* __restrict__ sizep,
             const float* __restrict__ gt_box,
             const int* __restrict__ gt_class,
             float* __restrict__ out) {
    __shared__ SmemU u;
    __shared__ int hist[256];
    __shared__ int wsum[8];
    __shared__ float wsf[8];
    __shared__ double wsd[8];
    __shared__ float s_w[NN], s_h[NN];
    __shared__ int s_ch[NN];
    __shared__ int s_last;
    __shared__ unsigned s_pfx;
    __shared__ int s_kth;
    __shared__ int s_eq;
    __shared__ int s_flag;

    const int tid = threadIdx.x;
    const int lane = tid & 31, wrp = tid >> 5;

    // Classic placement: smid = LUT[bid % 148]. Same residue -> same SM.
    // Residues 0..3 get all 32 batch blocks (8 per SM, no focal co-residents);
    // residues 4..147 carry the 1152-block focal stream.
    const int res = (int)blockIdx.x % NSM;
    const int layer = (int)blockIdx.x / NSM;   // 0..7

    if (res >= BRES) {
        // ================= focal partial (144 SMs, 8 blocks each) =================
        const int f = layer * (NSM - BRES) + (res - BRES);   // 0..1151
        const int total4 = BB * CC * HH * WW / 4;
        const int stride = FBLK * TPB;
        int i = f * TPB + tid;
        float a0 = 0.f, a1 = 0.f, a2 = 0.f, a3 = 0.f;
        for (; i + 3 * stride < total4; i += 4 * stride) {
            float4 v0 = cls4[i];
            float4 v1 = cls4[i + stride];
            float4 v2 = cls4[i + 2 * stride];
            float4 v3 = cls4[i + 3 * stride];
            a0 += nb2(v0.x) + nb2(v0.y) + nb2(v0.z) + nb2(v0.w);
            a1 += nb2(v1.x) + nb2(v1.y) + nb2(v1.z) + nb2(v1.w);
            a2 += nb2(v2.x) + nb2(v2.y) + nb2(v2.z) + nb2(v2.w);
            a3 += nb2(v3.x) + nb2(v3.y) + nb2(v3.z) + nb2(v3.w);
        }
        for (; i < total4; i += stride) {
            float4 v = cls4[i];
            a0 += nb2(v.x) + nb2(v.y) + nb2(v.z) + nb2(v.w);
        }
        float v = (a0 + a1) + (a2 + a3);
        #pragma unroll
        for (int o = 16; o; o >>= 1) v += __shfl_down_sync(0xffffffffu, v, o);
        if (lane == 0) wsf[wrp] = v;
        __syncthreads();
        if (tid == 0) {
            float s = 0.f;
            #pragma unroll
            for (int k = 0; k < 8; k++) s += wsf[k];
            g_focal[f] = (double)s * LN2;
        }
    } else {
        const int bidx = layer * BRES + res;   // 0..31 on 4 dedicated SMs
        if (bidx < BB) {
        // ========== type A: gt hash-dedup + focal corrections ==========
        const int b = bidx;
        const float* clsb = cls + (size_t)b * CC * HH * WW;

        for (int s = tid; s < HSZ; s += TPB) { u.a.hkey[s] = HEMPTY; u.a.hval[s] = 0u; }
        __syncthreads();

        if (tid < NN) {
            int clsv = gt_class[b * NN + tid];
            float4 bx = ((const float4*)gt_box)[b * NN + tid];
            if (clsv != -1) {
                int ch = max(clsv, 0);
                float wv = bx.z - bx.x;
                float hv = bx.w - bx.y;
                int cx = (int)floorf(floorf(wv * 0.5f) * 0.25f);
                int cy = (int)floorf(floorf(hv * 0.5f) * 0.25f);
                const float ONE_V = 0.6065306597126334f;   // exp(-0.5)
                const float TWO_V = 0.36787944117144233f;  // exp(-1.0)
                bool interior = (cx >= 1) && (cy >= 1) && (cx + 1 < HH) && (cy + 1 < WW);
                #pragma unroll
                for (int k = 0; k < 9; k++) {
                    int dx = k / 3 - 1, dy = k % 3 - 1;
                    float vv;
                    if (dx == 0 && dy == 0) {
                        if (cx < 0 || cx >= HH || cy < 0 || cy >= WW) continue;
                        vv = 1.0f;
                    } else {
                        if (!interior) continue;
                        vv = (dx != 0 && dy != 0) ? TWO_V : ONE_V;
                    }
                    unsigned cell = (unsigned)(((ch * HH + cx + dx) * WW) + cy + dy);
                    unsigned slot = (cell * 2654435761u) & (HSZ - 1);
                    while (true) {
                        unsigned prev = atomicCAS(&u.a.hkey[slot], HEMPTY, cell);
                        if (prev == HEMPTY || prev == cell) {
                            atomicMax(&u.a.hval[slot], __float_as_uint(vv));
                            break;
                        }
                        slot = (slot + 1) & (HSZ - 1);
                    }
                }
            }
        }
        __syncthreads();

        float corr = 0.f;
        for (int s = tid; s < HSZ; s += TPB) {
            unsigned cell = u.a.hkey[s];
            if (cell != HEMPTY) {
                float g = __uint_as_float(u.a.hval[s]);
                float p = clampp(clsb[cell]);
                float base = p * p * __logf(1.0f - p);
                float actual;
                if (g == 1.0f) {
                    float q = 1.0f - p, q2 = q * q;
                    actual = q2 * q2 * __logf(p);
                } else {
                    float q = 1.0f - g, q2 = q * q;
                    actual = q2 * q2 * base;
                }
                corr += actual - base;
            }
        }
        #pragma unroll
        for (int o = 16; o; o >>= 1) corr += __shfl_down_sync(0xffffffffu, corr, o);
        if (lane == 0) wsf[wrp] = corr;
        __syncthreads();
        if (tid == 0) {
            float s = 0.f;
            #pragma unroll
            for (int k = 0; k < 8; k++) s += wsf[k];
            g_corr[b] = s;
        }
        } else {
        // ========== type B: top-CANDK select + offset/size loss ==========
        const int b = bidx - BB;
        const float* clsb = cls + (size_t)b * CC * HH * WW;

        if (tid == 0) s_last = -1;
        __syncthreads();
        if (tid < NN) {
            int clsv = gt_class[b * NN + tid];
            float4 bx = ((const float4*)gt_box)[b * NN + tid];
            s_w[tid] = bx.z - bx.x;
            s_h[tid] = bx.w - bx.y;
            s_ch[tid] = max(clsv, 0);
            if (clsv != -1) atomicMax(&s_last, tid);
        }
        __syncthreads();

        int last = s_last;
        float sO = 0.f, sS = 0.f;
        int K = 0;
        float wv = 0.f, hv = 0.f;
        if (last >= 0) {
            wv = s_w[last];
            hv = s_h[last];
            int ch = s_ch[last];
            int cx = (int)floorf(floorf(wv * 0.5f) * 0.25f);
            int cy = (int)floorf(floorf(hv * 0.5f) * 0.25f);
            int w4 = (int)floorf(wv * 0.25f);
            int h4 = (int)floorf(hv * 0.25f);
            int left   = max((cx - (w4 >> 1)) >> 1, 0);   // >>1 == floor-div 2
            int right  = min((cx + (w4 >> 1)) >> 1, HH / 2);
            int top    = max((cy - (h4 >> 1)) >> 1, 0);
            int bottom = min((cy + (h4 >> 1)) >> 1, WW / 2);
            int wr = right - left, hc = bottom - top;
            int M = (wr > 0 && hc > 0) ? wr * hc : 0;
            M = min(M, KARR);    // guaranteed by input ranges; safety clamp
            K = min(CANDK, M);
            if (M > 0) {
                int Mr = (M + TPB - 1) & ~(TPB - 1);   // <= KARR
                for (int t = tid; t < M; t += TPB) {
                    int r = left + t / hc;
                    int c = top + t % hc;
                    int rc = r * WW + c;
                    float vv = clsb[ch * HH * WW + rc];
                    u.b.keys_v[t] = __float_as_uint(vv);
                    u.b.keys_i[t] = (unsigned short)rc;
                }
                for (int t = M + tid; t < Mr; t += TPB) u.b.keys_v[t] = 0xFFFFFFFFu;
                __syncthreads();

                unsigned V = 0xFFFFFFFFu;   // M <= K: select all
                unsigned Ti = 0xFFFFu;      // inclusive index threshold at v==V
                if (M > K) {
                    // ---- 4-pass radix-select of Kth smallest VALUE ----
                    if (tid == 0) { s_pfx = 0u; s_kth = K; }
                    __syncthreads();
                    #pragma unroll
                    for (int pi = 0; pi < 4; pi++) {
                        const int d = 24 - 8 * pi;
                        hist[tid] = 0;
                        __syncthreads();
                        unsigned pfx = s_pfx;
                        int kth = s_kth;
                        for (int i = tid; i < Mr; i += TPB) {
                            unsigned v = u.b.keys_v[i];
                            if (pi == 0 || (v >> (d + 8)) == pfx)
                                atomicAdd(&hist[(v >> d) & 255], 1);
                        }
                        __syncthreads();
                        int h0 = hist[tid];
                        int h = h0;
                        #pragma unroll
                        for (int o = 1; o < 32; o <<= 1) {
                            int n = __shfl_up_sync(0xffffffffu, h, o);
                            if (lane >= o) h += n;
                        }
                        if (lane == 31) wsum[wrp] = h;
                        __syncthreads();
                        if (tid < 8) {
                            int s = wsum[tid];
                            #pragma unroll
                            for (int o = 1; o < 8; o <<= 1) {
                                int n = __shfl_up_sync(0xffu, s, o);
                                if (tid >= o) s += n;
                            }
                            wsum[tid] = s;
                        }
                        __syncthreads();
                        int cum = h + (wrp ? wsum[wrp - 1] : 0);
                        if (cum - h0 < kth && kth <= cum) {   // exactly one thread
                            s_kth = kth - (cum - h0);
                            s_pfx = (pfx << 8) | (unsigned)tid;
                            if (pi == 3) s_eq = h0;
                        }
                        __syncthreads();
                    }
                    V = s_pfx;
                    int needed = s_kth, eqc = s_eq;
                    if (needed < eqc) {
                        // ---- rare: tie-break on index (2x7-bit radix) ----
                        if (tid == 0) s_pfx = 0u;
                        __syncthreads();
                        #pragma unroll
                        for (int pi = 0; pi < 2; pi++) {
                            const int d = 7 - 7 * pi;
                            if (tid < 128) hist[tid] = 0;
                            __syncthreads();
                            unsigned pfx = s_pfx;
                            int kth = s_kth;
                            for (int i = tid; i < Mr; i += TPB) {
                                if (u.b.keys_v[i] == V) {
                                    unsigned ix = u.b.keys_i[i];
                                    if (pi == 0 || (ix >> (d + 7)) == pfx)
                                        atomicAdd(&hist[(ix >> d) & 127], 1);
                                }
                            }
                            __syncthreads();
                            if (tid < 128) {
                                int h0 = hist[tid];
                                int h = h0;
                                #pragma unroll
                                for (int o = 1; o < 32; o <<= 1) {
                                    int n = __shfl_up_sync(0xffffffffu, h, o);
                                    if (lane >= o) h += n;
                                }
                                if (lane == 31) wsum[wrp] = h;
                                __syncwarp();
                            }
                            __syncthreads();
                            if (tid < 4) {
                                int s = wsum[tid];
                                #pragma unroll
                                for (int o = 1; o < 4; o <<= 1) {
                                    int n = __shfl_up_sync(0xfu, s, o);
                                    if (tid >= o) s += n;
                                }
                                wsum[tid] = s;
                            }
                            __syncthreads();
                            if (tid < 128) {
                                int h0 = hist[tid];
                                int h = h0;
                                #pragma unroll
                                for (int o = 1; o < 32; o <<= 1) {
                                    int n = __shfl_up_sync(0xffffffffu, h, o);
                                    if (lane >= o) h += n;
                                }
                                int cum = h + (wrp ? wsum[wrp - 1] : 0);
                                if (cum - h0 < kth && kth <= cum) {
                                    s_kth = kth - (cum - h0);
                                    s_pfx = (s_pfx << 7) | (unsigned)tid;
                                }
                            }
                            __syncthreads();
                        }
                        Ti = s_pfx;   // include idx <= Ti among v==V
                    }
                }

                float cxf = wv * 0.5f * 0.25f;
                float cyf = hv * 0.5f * 0.25f;
                float off0 = cxf - floorf(cxf);
                float off1 = cyf - floorf(cyf);
                // final gather: only ~K (<=100) cells touch global memory
                for (int t = tid; t < M; t += TPB) {
                    unsigned v = u.b.keys_v[t];
                    unsigned ix = u.b.keys_i[t];
                    if (v < V || (v == V && ix <= Ti)) {
                        int rc = (int)ix;
                        float o0 = offp[(b * 2 + 0) * HH * WW + rc];
                        float o1 = offp[(b * 2 + 1) * HH * WW + rc];
                        float s0 = sizep[(b * 2 + 0) * HH * WW + rc];
                        float s1 = sizep[(b * 2 + 1) * HH * WW + rc];
                        sO += fabsf(o0 - off0) + fabsf(o1 - off1);
                        sS += fabsf(s0 - wv) + fabsf(s1 - hv);
                    }
                }
            }
        }
        #pragma unroll
        for (int o = 16; o; o >>= 1) {
            sO += __shfl_down_sync(0xffffffffu, sO, o);
            sS += __shfl_down_sync(0xffffffffu, sS, o);
        }
        __syncthreads();
        if (lane == 0) { wsf[wrp] = sO; wsd[wrp] = (double)sS; }
        __syncthreads();
        if (tid == 0) {
            float aO = 0.f, aS = 0.f;
            #pragma unroll
            for (int k = 0; k < 8; k++) { aO += wsf[k]; aS += (float)wsd[k]; }
            g_off[b] = aO;
            g_size[b] = aS;
            g_npos[b] = K;
        }
        }
    }

    // ================= last-block combine =================
    __threadfence();
    __syncthreads();
    if (tid == 0) s_flag = (atomicAdd(&g_done, 1) == NBLK - 1);
    __syncthreads();
    if (s_flag) {
        __threadfence();
        double acc = 0.0;
        for (int i2 = tid; i2 < FBLK; i2 += TPB) acc += g_focal[i2];
        #pragma unroll
        for (int o = 16; o; o >>= 1) acc += __shfl_down_sync(0xffffffffu, acc, o);
        if (lane == 0) wsd[wrp] = acc;
        __syncthreads();
        if (tid == 0) {
            double fsum = 0.0;
            #pragma unroll
            for (int k = 0; k < 8; k++) fsum += wsd[k];
            double corr = 0.0, offs = 0.0, szs = 0.0;
            int npos = 0;
            for (int b2 = 0; b2 < BB; b2++) {
                corr += (double)g_corr[b2];
                offs += (double)g_off[b2];
                szs  += (double)g_size[b2];
                npos += g_npos[b2];
            }
            double np = (double)max(npos, 1);
            double cls_loss = -(fsum + corr) / (double)(BB * HH * WW);
            out[0] = (float)(cls_loss + 0.1 * (szs / np) + (offs / np));
            g_done = 0;   // reset for next graph replay
        }
    }
}

extern "C" void kernel_launch(void* const* d_in, const int* in_sizes, int n_in,
                              void* d_out, int out_size) {
    const float* cls_pred    = (const float*)d_in[0];
    const float* offset_pred = (const float*)d_in[1];
    const float* size_pred   = (const float*)d_in[2];
    const float* gt_box      = (const float*)d_in[3];
    const int*   gt_class    = (const int*)d_in[4];
    float* out = (float*)d_out;
    (void)in_sizes; (void)n_in; (void)out_size;

    fused_kernel<<<NBLK, TPB>>>((const float4*)cls_pred, cls_pred,
                                offset_pred, size_pred, gt_box, gt_class, out);
}